// round 12
// baseline (speedup 1.0000x reference)
#include <cuda_runtime.h>
#include <cstdint>

// Shapes: b=4, c=256, H=W=64 -> n=4096, k=32
#define BB   4
#define CCH  256
#define NN   4096
#define KD   32
#define RTOT 320
#define TQ   128          // queries per CTA (attn)
#define TK   64           // key tile (attn)
#define NT   (NN / TK)    // 64 key tiles

#define QSTR 36               // padded row stride (floats) for Q/K
#define PSTR 36               // P row stride (uint32 = bf16x2), 32 cols + 4 pad
#define VSTR2 264             // V row stride (uint32 = bf16x2 key-pairs)
#define QTILE_F (TQ * QSTR)   // 4608 floats
#define KTILE_F (TK * QSTR)   // 2304 floats
#define VTILE_U (32 * VSTR2)  // 8448 uint32

// Global tile images (device globals; no cudaMalloc allowed)
__device__ __align__(1024) float    g_Qimg[BB * 32 * QTILE_F];
__device__ __align__(1024) float    g_Kimg[BB * NT * KTILE_F];
__device__ __align__(1024) uint32_t g_Vimg[BB * NT * VTILE_U];  // bf16x2 packed

// ---------------------------------------------------------------------------
// PTX helpers (compute_100-safe: no tcgen05)
// ---------------------------------------------------------------------------
__device__ __forceinline__ uint32_t smem_u32(const void* p) {
    uint32_t a;
    asm("{ .reg .u64 t; cvta.to.shared.u64 t, %1; cvt.u32.u64 %0, t; }" : "=r"(a) : "l"(p));
    return a;
}

#define MBINIT(a, c)   asm volatile("mbarrier.init.shared.b64 [%0], %1;" :: "r"(a), "r"(c) : "memory")
#define MBEXPECT(a, n) asm volatile("mbarrier.arrive.expect_tx.shared.b64 _, [%0], %1;" :: "r"(a), "r"(n) : "memory")

#define MBWAIT(a, ph) do { \
    uint32_t _m = (a), _p = (ph), _d; \
    asm volatile("{\n\t.reg .pred p;\n\tmbarrier.try_wait.parity.shared.b64 p, [%1], %2;\n\tselp.b32 %0, 1, 0, p;\n\t}" \
        : "=r"(_d) : "r"(_m), "r"(_p) : "memory"); \
    if (!_d) { \
        asm volatile("{\n\t.reg .pred P1;\n\tWL_%=:\n\tmbarrier.try_wait.parity.shared.b64 P1, [%0], %1;\n\t@P1 bra.uni WD_%=;\n\tbra.uni WL_%=;\n\tWD_%=:\n\t}" \
            :: "r"(_m), "r"(_p) : "memory"); \
    } \
} while (0)

#define BULK_G2S(dst, src, bytes, mbar) \
    asm volatile("cp.async.bulk.shared::cluster.global.mbarrier::complete_tx::bytes [%0], [%1], %2, [%3];" \
        :: "r"(dst), "l"(src), "r"(bytes), "r"(mbar) : "memory")

#define STSH(a, v) asm volatile("st.shared.b32 [%0], %1;" :: "r"(a), "r"(v) : "memory")

__device__ __forceinline__ float tf32r(float x) {
    uint32_t y;
    asm("cvt.rna.tf32.f32 %0, %1;" : "=r"(y) : "f"(x));
    return __uint_as_float(y);
}

__device__ __forceinline__ uint32_t bf16x2(float lo, float hi) {
    uint32_t u;
    asm("cvt.rn.bf16x2.f32 %0, %1, %2;" : "=r"(u) : "f"(hi), "f"(lo));
    return u;
}

// tf32 m16n8k8: D += A(16x8) * B(8x8)
__device__ __forceinline__ void mma8(float& d0, float& d1, float& d2, float& d3,
                                     float a0, float a1, float a2, float a3,
                                     float b0, float b1) {
    asm volatile("mma.sync.aligned.m16n8k8.row.col.f32.tf32.tf32.f32 "
        "{%0,%1,%2,%3}, {%4,%5,%6,%7}, {%8,%9}, {%0,%1,%2,%3};"
        : "+f"(d0), "+f"(d1), "+f"(d2), "+f"(d3)
        : "r"(__float_as_uint(a0)), "r"(__float_as_uint(a1)),
          "r"(__float_as_uint(a2)), "r"(__float_as_uint(a3)),
          "r"(__float_as_uint(b0)), "r"(__float_as_uint(b1)));
}

// bf16 m16n8k16: D += A(16x16) * B(16x8)
__device__ __forceinline__ void mma16(float& d0, float& d1, float& d2, float& d3,
                                      uint32_t a0, uint32_t a1, uint32_t a2, uint32_t a3,
                                      uint32_t b0, uint32_t b1) {
    asm volatile("mma.sync.aligned.m16n8k16.row.col.f32.bf16.bf16.f32 "
        "{%0,%1,%2,%3}, {%4,%5,%6,%7}, {%8,%9}, {%0,%1,%2,%3};"
        : "+f"(d0), "+f"(d1), "+f"(d2), "+f"(d3)
        : "r"(a0), "r"(a1), "r"(a2), "r"(a3), "r"(b0), "r"(b1));
}

// One 16-key PV chunk for a 32-row warp: O(32x64) += P@V
__device__ __forceinline__ void pv_chunk(const uint32_t* __restrict__ Pr,
                                         const uint32_t* __restrict__ V,
                                         float (&o)[2][8][4],
                                         int q0b, int g, int tg, int nj, int ksq) {
    uint32_t af[2][4];
#pragma unroll
    for (int mt = 0; mt < 2; ++mt) {
        int base = (q0b + mt * 16 + g) * PSTR + ksq * 8 + tg;
        af[mt][0] = Pr[base];
        af[mt][1] = Pr[base + 8 * PSTR];
        af[mt][2] = Pr[base + 4];
        af[mt][3] = Pr[base + 8 * PSTR + 4];
    }
#pragma unroll
    for (int nt = 0; nt < 8; ++nt) {
        int vb = (ksq * 8 + tg) * VSTR2 + nj * 64 + nt * 8 + g;
        uint32_t b0 = V[vb], b1 = V[vb + 4 * VSTR2];
#pragma unroll
        for (int mt = 0; mt < 2; ++mt)
            mma16(o[mt][nt][0], o[mt][nt][1], o[mt][nt][2], o[mt][nt][3],
                  af[mt][0], af[mt][1], af[mt][2], af[mt][3], b0, b1);
    }
}

// ---------------------------------------------------------------------------
// Kernel 1: tf32 MMA projections -> tile images (unchanged)
// ---------------------------------------------------------------------------
#define XCS 72
#define WCS 68
#define OTS 324
#define PJ_WC 4608
#define PJ_SMEM ((PJ_WC + RTOT * WCS) * 4)

__global__ __launch_bounds__(256)
void proj_kernel(const float* __restrict__ t_in,
                 const float* __restrict__ f_w, const float* __restrict__ f_b,
                 const float* __restrict__ g_w, const float* __restrict__ g_b,
                 const float* __restrict__ h_w, const float* __restrict__ h_b)
{
    extern __shared__ float smf[];
    float* xc = smf;             // [64][XCS]
    float* wc = smf + PJ_WC;     // [320][WCS]
    float* ot = smf;             // [64][OTS] (union)

    const int tid  = threadIdx.x;
    const int w    = tid >> 5, lane = tid & 31;
    const int g    = lane >> 2, tg = lane & 3;
    const int b    = blockIdx.y;
    const int kt   = blockIdx.x;      // 64-pixel tile == one K/V tile
    const int n0   = kt * 64;
    const int wb   = w * 40;

    float acc[4][5][4];
#pragma unroll
    for (int mt = 0; mt < 4; ++mt)
#pragma unroll
        for (int nt = 0; nt < 5; ++nt)
#pragma unroll
            for (int r = 0; r < 4; ++r) acc[mt][nt][r] = 0.f;

    for (int cc = 0; cc < CCH; cc += 64) {
        __syncthreads();
        for (int idx = tid; idx < 64 * 16; idx += 256) {
            int c = idx >> 4, p4 = idx & 15;
            float4 v = *reinterpret_cast<const float4*>(
                t_in + (b * CCH + cc + c) * NN + n0 + p4 * 4);
            *reinterpret_cast<float4*>(xc + c * XCS + p4 * 4) = v;
        }
        for (int idx = tid; idx < RTOT * 16; idx += 256) {
            int r = idx >> 4, c4 = idx & 15;
            const float* wrow = (r < 32) ? (f_w + r * CCH)
                              : (r < 64) ? (g_w + (r - 32) * CCH)
                                         : (h_w + (r - 64) * CCH);
            float4 v = *reinterpret_cast<const float4*>(wrow + cc + c4 * 4);
            *reinterpret_cast<float4*>(wc + r * WCS + c4 * 4) = v;
        }
        __syncthreads();

#pragma unroll
        for (int ks = 0; ks < 8; ++ks) {
            float bf[5][2];
#pragma unroll
            for (int nt = 0; nt < 5; ++nt) {
                int kb = (wb + nt * 8 + g) * WCS + ks * 8 + tg;
                bf[nt][0] = wc[kb];
                bf[nt][1] = wc[kb + 4];
            }
#pragma unroll
            for (int mt = 0; mt < 4; ++mt) {
                int xa = (ks * 8 + tg) * XCS + mt * 16 + g;
                float a0 = xc[xa], a1 = xc[xa + 8];
                float a2 = xc[xa + 4 * XCS], a3 = xc[xa + 4 * XCS + 8];
#pragma unroll
                for (int nt = 0; nt < 5; ++nt)
                    mma8(acc[mt][nt][0], acc[mt][nt][1], acc[mt][nt][2], acc[mt][nt][3],
                         a0, a1, a2, a3, bf[nt][0], bf[nt][1]);
            }
        }
    }

    __syncthreads();
#pragma unroll
    for (int nt = 0; nt < 5; ++nt) {
        int r0 = wb + nt * 8 + 2 * tg;
        float b0 = (r0 < 32) ? f_b[r0] : (r0 < 64) ? g_b[r0 - 32] : h_b[r0 - 64];
        int r1 = r0 + 1;
        float b1 = (r1 < 32) ? f_b[r1] : (r1 < 64) ? g_b[r1 - 32] : h_b[r1 - 64];
#pragma unroll
        for (int mt = 0; mt < 4; ++mt) {
            int p0 = mt * 16 + g;
            ot[p0 * OTS + r0]       = acc[mt][nt][0] + b0;
            ot[p0 * OTS + r1]       = acc[mt][nt][1] + b1;
            ot[(p0 + 8) * OTS + r0] = acc[mt][nt][2] + b0;
            ot[(p0 + 8) * OTS + r1] = acc[mt][nt][3] + b1;
        }
    }
    __syncthreads();

    // K image (f-proj, rows 0..31)
    for (int e = tid; e < 64 * KD; e += 256) {
        int p = e >> 5, d = e & 31;
        g_Kimg[(b * NT + kt) * KTILE_F + p * QSTR + d] = tf32r(ot[p * OTS + d]);
    }
    // Q image (g-proj, rows 32..63)
    for (int e = tid; e < 64 * KD; e += 256) {
        int p = e >> 5, d = e & 31;
        g_Qimg[(b * 32 + (kt >> 1)) * QTILE_F + ((kt & 1) * 64 + p) * QSTR + d]
            = tf32r(ot[p * OTS + 32 + d]);
    }
    // V image (h-proj, rows 64..319): bf16x2 key-pairs
    for (int e = tid; e < 32 * CCH; e += 256) {
        int kp = e >> 8, c = e & 255;
        g_Vimg[(b * NT + kt) * VTILE_U + kp * VSTR2 + c]
            = bf16x2(ot[(kp * 2) * OTS + 64 + c], ot[(kp * 2 + 1) * OTS + 64 + c]);
    }
}

// ---------------------------------------------------------------------------
// Kernel 2: tf32-QK / bf16-PV flash attention. TQ=128, TK=64, 512 threads
// (16 warps, 4/SMSP), 3-slot KV pipeline, one barrier per tile.
// Warp (mi = w>>2, nj = w&3): QK rows mi*32..+31 x keys nj*16..+15;
//                             PV rows mi*32..+31 x ch nj*64..+63.
// ---------------------------------------------------------------------------
#define SB_Q   0
#define SB_K   18432               // 3 slots x 9216 B
#define SB_V   46080               // 3 slots x 33792 B
#define SB_P   147456              // 2 bufs x 18432 B
#define SB_L   184320
#define SB_MB  184832
#define SB_TOTAL 184896
#define KSLOT_B 9216
#define VSLOT_B 33792

__global__ __launch_bounds__(512, 1)
void attn_kernel(const float* __restrict__ t_in,
                 const float* __restrict__ gamma,
                 float* __restrict__ out)
{
    extern __shared__ float smf[];
    const uint32_t sb = smem_u32(smf);
    const int tid  = threadIdx.x;
    const int w    = tid >> 5, lane = tid & 31;
    const int g    = lane >> 2, tg = lane & 3;
    const int mi   = w >> 2,   nj = w & 3;
    const int b    = blockIdx.y, qt = blockIdx.x;
    const int n0   = qt * TQ;
    const int q0b  = mi * 32;

    float*    Qs = smf;
    float*    Ks = smf + 4608;
    uint32_t* Vs = reinterpret_cast<uint32_t*>(smf) + 11520;
    uint32_t* Pb = reinterpret_cast<uint32_t*>(smf) + 36864;
    float*    Lr = smf + 46080;
    const uint32_t mb = sb + SB_MB;   // mbars 0..2: KV slots, 3: Q

    // P-store byte offsets: warp's keys are nj*16 + kn*8; pair cols nj*8+kn*4+tg
    uint32_t prow[2];
#pragma unroll
    for (int mt = 0; mt < 2; ++mt)
        prow[mt] = (uint32_t)(((q0b + mt * 16 + g) * PSTR + nj * 8 + tg) * 4);

    if (tid == 0) {
#pragma unroll
        for (int i = 0; i < 4; ++i) MBINIT(mb + i * 8, 1);
        MBEXPECT(mb + 24, QTILE_F * 4);
        BULK_G2S(sb + SB_Q, g_Qimg + (b * 32 + qt) * QTILE_F, QTILE_F * 4, mb + 24);
        for (int s = 0; s < 2; ++s) {
            MBEXPECT(mb + s * 8, KSLOT_B + VSLOT_B);
            BULK_G2S(sb + SB_K + s * KSLOT_B,
                     g_Kimg + (b * NT + s) * KTILE_F, KSLOT_B, mb + s * 8);
            BULK_G2S(sb + SB_V + s * VSLOT_B,
                     g_Vimg + (b * NT + s) * VTILE_U, VSLOT_B, mb + s * 8);
        }
    }
    if (tid < 128) Lr[tid] = 0.f;
    __syncthreads();

    MBWAIT(mb + 24, 0);
    float qf[2][4][4];
#pragma unroll
    for (int mt = 0; mt < 2; ++mt)
#pragma unroll
        for (int ks = 0; ks < 4; ++ks) {
            int r0 = (q0b + mt * 16 + g) * QSTR + ks * 8 + tg;
            qf[mt][ks][0] = Qs[r0];
            qf[mt][ks][1] = Qs[r0 + 8 * QSTR];
            qf[mt][ks][2] = Qs[r0 + 4];
            qf[mt][ks][3] = Qs[r0 + 8 * QSTR + 4];
        }

    float o[2][8][4];
#pragma unroll
    for (int mt = 0; mt < 2; ++mt)
#pragma unroll
        for (int nt = 0; nt < 8; ++nt)
#pragma unroll
            for (int r = 0; r < 4; ++r) o[mt][nt][r] = 0.f;
    float lsum[2][2];
#pragma unroll
    for (int mt = 0; mt < 2; ++mt) { lsum[mt][0] = 0.f; lsum[mt][1] = 0.f; }

// exp chunk: exp(sf[mt][kn]) -> bf16x2 -> lsum (rounded) -> pinned STS
#define EXP_CHUNK(mt, kn) do { \
    float p0 = __expf(sf[mt][kn][0]), p1 = __expf(sf[mt][kn][1]); \
    float p2 = __expf(sf[mt][kn][2]), p3 = __expf(sf[mt][kn][3]); \
    uint32_t u01, u23; \
    asm volatile("cvt.rn.bf16x2.f32 %0, %1, %2;" : "=r"(u01) : "f"(p1), "f"(p0)); \
    asm volatile("cvt.rn.bf16x2.f32 %0, %1, %2;" : "=r"(u23) : "f"(p3), "f"(p2)); \
    lsum[mt][0] += __uint_as_float(u01 << 16) + __uint_as_float(u01 & 0xffff0000u); \
    lsum[mt][1] += __uint_as_float(u23 << 16) + __uint_as_float(u23 & 0xffff0000u); \
    STSH(pw_base + prow[mt] + (kn) * 16, u01); \
    STSH(pw_base + prow[mt] + (kn) * 16 + 8 * PSTR * 4, u23); \
} while (0)

    for (int t = 0; t < NT; ++t) {
        const int s = t % 3;
        MBWAIT(mb + s * 8, (t / 3) & 1);
        const float*    K  = Ks + s * KTILE_F;
        const uint32_t* Pr = Pb + ((t - 1) & 1) * 4608;
        const uint32_t  pw_base = sb + SB_P + (uint32_t)(t & 1) * 18432;
        const uint32_t* Vprev = Vs + (((t - 1) % 3 + 3) % 3) * VTILE_U;

        // S(t): rows q0b..+31 x keys nj*16..+15 (2 mt x 2 kn tiles)
        float sf[2][2][4];
#pragma unroll
        for (int mt = 0; mt < 2; ++mt)
#pragma unroll
            for (int kn = 0; kn < 2; ++kn)
#pragma unroll
                for (int r = 0; r < 4; ++r) sf[mt][kn][r] = 0.f;
#pragma unroll
        for (int ks = 0; ks < 4; ++ks)
#pragma unroll
            for (int kn = 0; kn < 2; ++kn) {
                int kb = (nj * 16 + kn * 8 + g) * QSTR + ks * 8 + tg;
                float b0 = K[kb], b1 = K[kb + 4];
#pragma unroll
                for (int mt = 0; mt < 2; ++mt)
                    mma8(sf[mt][kn][0], sf[mt][kn][1], sf[mt][kn][2], sf[mt][kn][3],
                         qf[mt][ks][0], qf[mt][ks][1], qf[mt][ks][2], qf[mt][ks][3],
                         b0, b1);
            }

        // PV(t-1) chunks interleaved with exp(t)
        if (t > 0) {
            pv_chunk(Pr, Vprev, o, q0b, g, tg, nj, 0);
            EXP_CHUNK(0, 0);
            EXP_CHUNK(0, 1);
            pv_chunk(Pr, Vprev, o, q0b, g, tg, nj, 1);
            EXP_CHUNK(1, 0);
            EXP_CHUNK(1, 1);
            pv_chunk(Pr, Vprev, o, q0b, g, tg, nj, 2);
            pv_chunk(Pr, Vprev, o, q0b, g, tg, nj, 3);
        } else {
            EXP_CHUNK(0, 0); EXP_CHUNK(0, 1);
            EXP_CHUNK(1, 0); EXP_CHUNK(1, 1);
        }
        __syncthreads();   // P(t) visible; PV(t-1) complete; slot (t-1)%3 free

        if (tid == 0 && t + 2 < NT) {
            int u = t + 2, s2 = u % 3;
            MBEXPECT(mb + s2 * 8, KSLOT_B + VSLOT_B);
            BULK_G2S(sb + SB_K + s2 * KSLOT_B,
                     g_Kimg + (b * NT + u) * KTILE_F, KSLOT_B, mb + s2 * 8);
            BULK_G2S(sb + SB_V + s2 * VSLOT_B,
                     g_Vimg + (b * NT + u) * VTILE_U, VSLOT_B, mb + s2 * 8);
        }
    }

    // Drain: PV for the last tile
    {
        const uint32_t* Pr = Pb + ((NT - 1) & 1) * 4608;
        const uint32_t* V  = Vs + ((NT - 1) % 3) * VTILE_U;
#pragma unroll
        for (int ksq = 0; ksq < 4; ++ksq)
            pv_chunk(Pr, V, o, q0b, g, tg, nj, ksq);
    }

    // Row-sum reduction: quad shuffle then cross-warp atomic (over nj)
#pragma unroll
    for (int mt = 0; mt < 2; ++mt)
#pragma unroll
        for (int h = 0; h < 2; ++h) {
            float v = lsum[mt][h];
            v += __shfl_xor_sync(0xffffffffu, v, 1);
            v += __shfl_xor_sync(0xffffffffu, v, 2);
            if (tg == 0) atomicAdd(&Lr[q0b + mt * 16 + h * 8 + g], v);
        }
    __syncthreads();

    const float gam = gamma[0];
#pragma unroll
    for (int mt = 0; mt < 2; ++mt) {
        const float s0 = gam / Lr[q0b + mt * 16 + g];
        const float s1 = gam / Lr[q0b + mt * 16 + 8 + g];
        const int qg = n0 + q0b + mt * 16 + g;
#pragma unroll
        for (int nt = 0; nt < 8; ++nt) {
            int c  = nj * 64 + nt * 8 + 2 * tg;
            int i0 = (b * CCH + c) * NN + qg;
            out[i0]          = o[mt][nt][0] * s0 + t_in[i0];
            out[i0 + NN]     = o[mt][nt][1] * s0 + t_in[i0 + NN];
            out[i0 + 8]      = o[mt][nt][2] * s1 + t_in[i0 + 8];
            out[i0 + NN + 8] = o[mt][nt][3] * s1 + t_in[i0 + NN + 8];
        }
    }
}

// ---------------------------------------------------------------------------
extern "C" void kernel_launch(void* const* d_in, const int* in_sizes, int n_in,
                              void* d_out, int out_size)
{
    const float* t_in  = (const float*)d_in[0];
    const float* f_w   = (const float*)d_in[1];
    const float* f_b   = (const float*)d_in[2];
    const float* g_w   = (const float*)d_in[3];
    const float* g_b   = (const float*)d_in[4];
    const float* h_w   = (const float*)d_in[5];
    const float* h_b   = (const float*)d_in[6];
    const float* gamma = (const float*)d_in[7];
    float* out = (float*)d_out;

    cudaFuncSetAttribute(proj_kernel,
                         cudaFuncAttributeMaxDynamicSharedMemorySize, PJ_SMEM);
    cudaFuncSetAttribute(attn_kernel,
                         cudaFuncAttributeMaxDynamicSharedMemorySize, SB_TOTAL);

    proj_kernel<<<dim3(64, BB), 256, PJ_SMEM>>>(t_in, f_w, f_b, g_w, g_b, h_w, h_b);
    attn_kernel<<<dim3(NN / TQ, BB), 512, SB_TOTAL>>>(t_in, gamma, out);
}

// round 13
// speedup vs baseline: 1.1259x; 1.1259x over previous
#include <cuda_runtime.h>
#include <cstdint>

// Shapes: b=4, c=256, H=W=64 -> n=4096, k=32
#define BB   4
#define CCH  256
#define NN   4096
#define KD   32
#define RTOT 320
#define TQ   128          // queries per CTA (attn)
#define TK   64           // key tile (attn)
#define NT   (NN / TK)    // 64 key tiles

#define QSTR 36               // padded row stride (floats) for Q/K
#define PSTR 36               // P row stride (uint32 = bf16x2), 32 cols + 4 pad
#define VSTR2 264             // V row stride (uint32 = bf16x2 key-pairs)
#define QTILE_F (TQ * QSTR)   // 4608 floats
#define KTILE_F (TK * QSTR)   // 2304 floats
#define VTILE_U (32 * VSTR2)  // 8448 uint32

// Global tile images (device globals; no cudaMalloc allowed)
__device__ __align__(1024) float    g_Qimg[BB * 32 * QTILE_F];
__device__ __align__(1024) float    g_Kimg[BB * NT * KTILE_F];
__device__ __align__(1024) uint32_t g_Vimg[BB * NT * VTILE_U];  // bf16x2 packed

// ---------------------------------------------------------------------------
// PTX helpers (compute_100-safe: no tcgen05)
// ---------------------------------------------------------------------------
__device__ __forceinline__ uint32_t smem_u32(const void* p) {
    uint32_t a;
    asm("{ .reg .u64 t; cvta.to.shared.u64 t, %1; cvt.u32.u64 %0, t; }" : "=r"(a) : "l"(p));
    return a;
}

#define MBINIT(a, c)   asm volatile("mbarrier.init.shared.b64 [%0], %1;" :: "r"(a), "r"(c) : "memory")
#define MBEXPECT(a, n) asm volatile("mbarrier.arrive.expect_tx.shared.b64 _, [%0], %1;" :: "r"(a), "r"(n) : "memory")
#define MBARR(a)       asm volatile("mbarrier.arrive.shared.b64 _, [%0];" :: "r"(a) : "memory")

#define MBWAIT(a, ph) do { \
    uint32_t _m = (a), _p = (ph), _d; \
    asm volatile("{\n\t.reg .pred p;\n\tmbarrier.try_wait.parity.shared.b64 p, [%1], %2;\n\tselp.b32 %0, 1, 0, p;\n\t}" \
        : "=r"(_d) : "r"(_m), "r"(_p) : "memory"); \
    if (!_d) { \
        asm volatile("{\n\t.reg .pred P1;\n\tWL_%=:\n\tmbarrier.try_wait.parity.shared.b64 P1, [%0], %1;\n\t@P1 bra.uni WD_%=;\n\tbra.uni WL_%=;\n\tWD_%=:\n\t}" \
            :: "r"(_m), "r"(_p) : "memory"); \
    } \
} while (0)

#define BULK_G2S(dst, src, bytes, mbar) \
    asm volatile("cp.async.bulk.shared::cluster.global.mbarrier::complete_tx::bytes [%0], [%1], %2, [%3];" \
        :: "r"(dst), "l"(src), "r"(bytes), "r"(mbar) : "memory")

#define STSH(a, v) asm volatile("st.shared.b32 [%0], %1;" :: "r"(a), "r"(v) : "memory")

__device__ __forceinline__ float tf32r(float x) {
    uint32_t y;
    asm("cvt.rna.tf32.f32 %0, %1;" : "=r"(y) : "f"(x));
    return __uint_as_float(y);
}

__device__ __forceinline__ uint32_t bf16x2(float lo, float hi) {
    uint32_t u;
    asm("cvt.rn.bf16x2.f32 %0, %1, %2;" : "=r"(u) : "f"(hi), "f"(lo));
    return u;
}

// tf32 m16n8k8: D += A(16x8) * B(8x8)
__device__ __forceinline__ void mma8(float& d0, float& d1, float& d2, float& d3,
                                     float a0, float a1, float a2, float a3,
                                     float b0, float b1) {
    asm volatile("mma.sync.aligned.m16n8k8.row.col.f32.tf32.tf32.f32 "
        "{%0,%1,%2,%3}, {%4,%5,%6,%7}, {%8,%9}, {%0,%1,%2,%3};"
        : "+f"(d0), "+f"(d1), "+f"(d2), "+f"(d3)
        : "r"(__float_as_uint(a0)), "r"(__float_as_uint(a1)),
          "r"(__float_as_uint(a2)), "r"(__float_as_uint(a3)),
          "r"(__float_as_uint(b0)), "r"(__float_as_uint(b1)));
}

// bf16 m16n8k16: D += A(16x16) * B(16x8)
__device__ __forceinline__ void mma16(float& d0, float& d1, float& d2, float& d3,
                                      uint32_t a0, uint32_t a1, uint32_t a2, uint32_t a3,
                                      uint32_t b0, uint32_t b1) {
    asm volatile("mma.sync.aligned.m16n8k16.row.col.f32.bf16.bf16.f32 "
        "{%0,%1,%2,%3}, {%4,%5,%6,%7}, {%8,%9}, {%0,%1,%2,%3};"
        : "+f"(d0), "+f"(d1), "+f"(d2), "+f"(d3)
        : "r"(a0), "r"(a1), "r"(a2), "r"(a3), "r"(b0), "r"(b1));
}

// One 16-key PV chunk: O(64x64) += P[:, 16ksq..] @ V[16ksq.., :]
__device__ __forceinline__ void pv_chunk(const uint32_t* __restrict__ Pr,
                                         const uint32_t* __restrict__ V,
                                         float (&o)[4][8][4],
                                         int q0b, int g, int tg, int nj, int ksq) {
    uint32_t af[4][4];
#pragma unroll
    for (int mt = 0; mt < 4; ++mt) {
        int base = (q0b + mt * 16 + g) * PSTR + ksq * 8 + tg;
        af[mt][0] = Pr[base];
        af[mt][1] = Pr[base + 8 * PSTR];
        af[mt][2] = Pr[base + 4];
        af[mt][3] = Pr[base + 8 * PSTR + 4];
    }
#pragma unroll
    for (int nt = 0; nt < 8; ++nt) {
        int vb = (ksq * 8 + tg) * VSTR2 + nj * 64 + nt * 8 + g;
        uint32_t b0 = V[vb], b1 = V[vb + 4 * VSTR2];
#pragma unroll
        for (int mt = 0; mt < 4; ++mt)
            mma16(o[mt][nt][0], o[mt][nt][1], o[mt][nt][2], o[mt][nt][3],
                  af[mt][0], af[mt][1], af[mt][2], af[mt][3], b0, b1);
    }
}

// ---------------------------------------------------------------------------
// Kernel 1: tf32 MMA projections -> tile images (unchanged from R10)
// ---------------------------------------------------------------------------
#define XCS 72
#define WCS 68
#define OTS 324
#define PJ_WC 4608
#define PJ_SMEM ((PJ_WC + RTOT * WCS) * 4)

__global__ __launch_bounds__(256)
void proj_kernel(const float* __restrict__ t_in,
                 const float* __restrict__ f_w, const float* __restrict__ f_b,
                 const float* __restrict__ g_w, const float* __restrict__ g_b,
                 const float* __restrict__ h_w, const float* __restrict__ h_b)
{
    extern __shared__ float smf[];
    float* xc = smf;             // [64][XCS]
    float* wc = smf + PJ_WC;     // [320][WCS]
    float* ot = smf;             // [64][OTS] (union)

    const int tid  = threadIdx.x;
    const int w    = tid >> 5, lane = tid & 31;
    const int g    = lane >> 2, tg = lane & 3;
    const int b    = blockIdx.y;
    const int kt   = blockIdx.x;      // 64-pixel tile == one K/V tile
    const int n0   = kt * 64;
    const int wb   = w * 40;

    float acc[4][5][4];
#pragma unroll
    for (int mt = 0; mt < 4; ++mt)
#pragma unroll
        for (int nt = 0; nt < 5; ++nt)
#pragma unroll
            for (int r = 0; r < 4; ++r) acc[mt][nt][r] = 0.f;

    for (int cc = 0; cc < CCH; cc += 64) {
        __syncthreads();
        for (int idx = tid; idx < 64 * 16; idx += 256) {
            int c = idx >> 4, p4 = idx & 15;
            float4 v = *reinterpret_cast<const float4*>(
                t_in + (b * CCH + cc + c) * NN + n0 + p4 * 4);
            *reinterpret_cast<float4*>(xc + c * XCS + p4 * 4) = v;
        }
        for (int idx = tid; idx < RTOT * 16; idx += 256) {
            int r = idx >> 4, c4 = idx & 15;
            const float* wrow = (r < 32) ? (f_w + r * CCH)
                              : (r < 64) ? (g_w + (r - 32) * CCH)
                                         : (h_w + (r - 64) * CCH);
            float4 v = *reinterpret_cast<const float4*>(wrow + cc + c4 * 4);
            *reinterpret_cast<float4*>(wc + r * WCS + c4 * 4) = v;
        }
        __syncthreads();

#pragma unroll
        for (int ks = 0; ks < 8; ++ks) {
            float bf[5][2];
#pragma unroll
            for (int nt = 0; nt < 5; ++nt) {
                int kb = (wb + nt * 8 + g) * WCS + ks * 8 + tg;
                bf[nt][0] = wc[kb];
                bf[nt][1] = wc[kb + 4];
            }
#pragma unroll
            for (int mt = 0; mt < 4; ++mt) {
                int xa = (ks * 8 + tg) * XCS + mt * 16 + g;
                float a0 = xc[xa], a1 = xc[xa + 8];
                float a2 = xc[xa + 4 * XCS], a3 = xc[xa + 4 * XCS + 8];
#pragma unroll
                for (int nt = 0; nt < 5; ++nt)
                    mma8(acc[mt][nt][0], acc[mt][nt][1], acc[mt][nt][2], acc[mt][nt][3],
                         a0, a1, a2, a3, bf[nt][0], bf[nt][1]);
            }
        }
    }

    __syncthreads();
#pragma unroll
    for (int nt = 0; nt < 5; ++nt) {
        int r0 = wb + nt * 8 + 2 * tg;
        float b0 = (r0 < 32) ? f_b[r0] : (r0 < 64) ? g_b[r0 - 32] : h_b[r0 - 64];
        int r1 = r0 + 1;
        float b1 = (r1 < 32) ? f_b[r1] : (r1 < 64) ? g_b[r1 - 32] : h_b[r1 - 64];
#pragma unroll
        for (int mt = 0; mt < 4; ++mt) {
            int p0 = mt * 16 + g;
            ot[p0 * OTS + r0]       = acc[mt][nt][0] + b0;
            ot[p0 * OTS + r1]       = acc[mt][nt][1] + b1;
            ot[(p0 + 8) * OTS + r0] = acc[mt][nt][2] + b0;
            ot[(p0 + 8) * OTS + r1] = acc[mt][nt][3] + b1;
        }
    }
    __syncthreads();

    // K image (f-proj, rows 0..31)
    for (int e = tid; e < 64 * KD; e += 256) {
        int p = e >> 5, d = e & 31;
        g_Kimg[(b * NT + kt) * KTILE_F + p * QSTR + d] = tf32r(ot[p * OTS + d]);
    }
    // Q image (g-proj, rows 32..63)
    for (int e = tid; e < 64 * KD; e += 256) {
        int p = e >> 5, d = e & 31;
        g_Qimg[(b * 32 + (kt >> 1)) * QTILE_F + ((kt & 1) * 64 + p) * QSTR + d]
            = tf32r(ot[p * OTS + 32 + d]);
    }
    // V image (h-proj, rows 64..319): bf16x2 key-pairs
    for (int e = tid; e < 32 * CCH; e += 256) {
        int kp = e >> 8, c = e & 255;
        g_Vimg[(b * NT + kt) * VTILE_U + kp * VSTR2 + c]
            = bf16x2(ot[(kp * 2) * OTS + 64 + c], ot[(kp * 2 + 1) * OTS + 64 + c]);
    }
}

// ---------------------------------------------------------------------------
// Kernel 2: tf32-QK / bf16-PV flash attention. TQ=128, TK=64, 256 threads.
// Rendezvous-free tile pipeline: count-8 mbarrier (arrive after PV+P-store,
// wait only before consuming P(t-1)); QK+exp hoisted before the wait.
// 3 K slots, 4 V slots, 2 P buffers.
// ---------------------------------------------------------------------------
#define SB_Q   0
#define SB_K   18432               // 3 slots x 9216 B
#define SB_V   46080               // 4 slots x 33792 B
#define SB_P   181248              // 2 bufs x 18432 B
#define SB_L   218112
#define SB_MB  218624
#define SB_TOTAL 218752
#define KSLOT_B 9216
#define VSLOT_B 33792

__global__ __launch_bounds__(256, 1)
void attn_kernel(const float* __restrict__ t_in,
                 const float* __restrict__ gamma,
                 float* __restrict__ out)
{
    extern __shared__ float smf[];
    const uint32_t sb = smem_u32(smf);
    const int tid  = threadIdx.x;
    const int w    = tid >> 5, lane = tid & 31;
    const int g    = lane >> 2, tg = lane & 3;
    const int mi   = w >> 2,   nj = w & 3;
    const int b    = blockIdx.y, qt = blockIdx.x;
    const int n0   = qt * TQ;
    const int q0b  = mi * 64;

    float*    Qs = smf;
    float*    Ks = smf + 4608;
    uint32_t* Vs = reinterpret_cast<uint32_t*>(smf) + 11520;
    uint32_t* Pb = reinterpret_cast<uint32_t*>(smf) + 45312;
    float*    Lr = smf + 54528;
    const uint32_t mb_k    = sb + SB_MB;        // 3 x 8B
    const uint32_t mb_v    = sb + SB_MB + 24;   // 4 x 8B
    const uint32_t mb_q    = sb + SB_MB + 56;
    const uint32_t mb_pipe = sb + SB_MB + 64;   // count 8

    uint32_t prow[4];
#pragma unroll
    for (int mt = 0; mt < 4; ++mt)
        prow[mt] = (uint32_t)(((q0b + mt * 16 + g) * PSTR + 4 * nj + tg) * 4);

    if (tid == 0) {
#pragma unroll
        for (int i = 0; i < 3; ++i) MBINIT(mb_k + i * 8, 1);
#pragma unroll
        for (int i = 0; i < 4; ++i) MBINIT(mb_v + i * 8, 1);
        MBINIT(mb_q, 1);
        MBINIT(mb_pipe, 8);
        MBEXPECT(mb_q, QTILE_F * 4);
        BULK_G2S(sb + SB_Q, g_Qimg + (b * 32 + qt) * QTILE_F, QTILE_F * 4, mb_q);
        for (int s = 0; s < 2; ++s) {
            MBEXPECT(mb_k + s * 8, KSLOT_B);
            BULK_G2S(sb + SB_K + s * KSLOT_B,
                     g_Kimg + (b * NT + s) * KTILE_F, KSLOT_B, mb_k + s * 8);
            MBEXPECT(mb_v + s * 8, VSLOT_B);
            BULK_G2S(sb + SB_V + s * VSLOT_B,
                     g_Vimg + (b * NT + s) * VTILE_U, VSLOT_B, mb_v + s * 8);
        }
    }
    if (tid < 128) Lr[tid] = 0.f;
    __syncthreads();   // mbarrier inits + Lr visible

    MBWAIT(mb_q, 0);
    float qf[4][4][4];
#pragma unroll
    for (int mt = 0; mt < 4; ++mt)
#pragma unroll
        for (int ks = 0; ks < 4; ++ks) {
            int r0 = (q0b + mt * 16 + g) * QSTR + ks * 8 + tg;
            qf[mt][ks][0] = Qs[r0];
            qf[mt][ks][1] = Qs[r0 + 8 * QSTR];
            qf[mt][ks][2] = Qs[r0 + 4];
            qf[mt][ks][3] = Qs[r0 + 8 * QSTR + 4];
        }

    float o[4][8][4];
#pragma unroll
    for (int mt = 0; mt < 4; ++mt)
#pragma unroll
        for (int nt = 0; nt < 8; ++nt)
#pragma unroll
            for (int r = 0; r < 4; ++r) o[mt][nt][r] = 0.f;
    float lsum[4][2];
#pragma unroll
    for (int mt = 0; mt < 4; ++mt) { lsum[mt][0] = 0.f; lsum[mt][1] = 0.f; }

#define PSTORE(h, mt) do { \
    STSH(pw + prow[mt] + (h) * 64, pe[h][mt][0]); \
    STSH(pw + prow[mt] + (h) * 64 + 8 * PSTR * 4, pe[h][mt][1]); \
} while (0)

    for (int t = 0; t < NT; ++t) {
        const int sk = t % 3, sv = t & 3;
        MBWAIT(mb_k + sk * 8, (t / 3) & 1);
        MBWAIT(mb_v + sv * 8, (t >> 2) & 1);
        const float* K = Ks + sk * KTILE_F;

        // QK(t) + exp(t) -> registers (both halves), BEFORE the pipe wait
        uint32_t pe[2][4][2];
        float sf[4][4];
#pragma unroll
        for (int h = 0; h < 2; ++h) {
#pragma unroll
            for (int mt = 0; mt < 4; ++mt)
#pragma unroll
                for (int r = 0; r < 4; ++r) sf[mt][r] = 0.f;
#pragma unroll
            for (int ks = 0; ks < 4; ++ks) {
                int kb = (h * 32 + nj * 8 + g) * QSTR + ks * 8 + tg;
                float b0 = K[kb], b1 = K[kb + 4];
#pragma unroll
                for (int mt = 0; mt < 4; ++mt)
                    mma8(sf[mt][0], sf[mt][1], sf[mt][2], sf[mt][3],
                         qf[mt][ks][0], qf[mt][ks][1], qf[mt][ks][2], qf[mt][ks][3],
                         b0, b1);
            }
#pragma unroll
            for (int mt = 0; mt < 4; ++mt) {
                float p0 = __expf(sf[mt][0]), p1 = __expf(sf[mt][1]);
                float p2 = __expf(sf[mt][2]), p3 = __expf(sf[mt][3]);
                uint32_t u01 = bf16x2(p0, p1);
                uint32_t u23 = bf16x2(p2, p3);
                lsum[mt][0] += __uint_as_float(u01 << 16) + __uint_as_float(u01 & 0xffff0000u);
                lsum[mt][1] += __uint_as_float(u23 << 16) + __uint_as_float(u23 & 0xffff0000u);
                pe[h][mt][0] = u01;
                pe[h][mt][1] = u23;
            }
        }

        // Wait for tile (t-1) arrivals: P(t-1) stored by all, PV(t-2) done by all
        if (t > 0) MBWAIT(mb_pipe, (t - 1) & 1);

        // Prefetch t+2 (safe: arrives(t-1) imply QK(t-1) + PV(t-2) reads done)
        if (tid == 0 && t + 2 < NT) {
            int u = t + 2;
            MBEXPECT(mb_k + (u % 3) * 8, KSLOT_B);
            BULK_G2S(sb + SB_K + (u % 3) * KSLOT_B,
                     g_Kimg + (b * NT + u) * KTILE_F, KSLOT_B, mb_k + (u % 3) * 8);
            MBEXPECT(mb_v + (u & 3) * 8, VSLOT_B);
            BULK_G2S(sb + SB_V + (u & 3) * VSLOT_B,
                     g_Vimg + (b * NT + u) * VTILE_U, VSLOT_B, mb_v + (u & 3) * 8);
        }

        // PV(t-1) interleaved with P(t) stores
        const uint32_t* Pr = Pb + ((t - 1) & 1) * 4608;
        const uint32_t  pw = sb + SB_P + (uint32_t)(t & 1) * 18432;
        const uint32_t* Vprev = Vs + ((t - 1) & 3) * VTILE_U;
        if (t > 0) {
            pv_chunk(Pr, Vprev, o, q0b, g, tg, nj, 0);
            PSTORE(0, 0); PSTORE(0, 1);
            pv_chunk(Pr, Vprev, o, q0b, g, tg, nj, 1);
            PSTORE(0, 2); PSTORE(0, 3);
            pv_chunk(Pr, Vprev, o, q0b, g, tg, nj, 2);
            PSTORE(1, 0); PSTORE(1, 1);
            pv_chunk(Pr, Vprev, o, q0b, g, tg, nj, 3);
            PSTORE(1, 2); PSTORE(1, 3);
        } else {
            PSTORE(0, 0); PSTORE(0, 1); PSTORE(0, 2); PSTORE(0, 3);
            PSTORE(1, 0); PSTORE(1, 1); PSTORE(1, 2); PSTORE(1, 3);
        }
        if (lane == 0) MBARR(mb_pipe);
    }

    // Drain: wait final arrivals, then PV(NT-1)
    MBWAIT(mb_pipe, (NT - 1) & 1);
    {
        const uint32_t* Pr = Pb + ((NT - 1) & 1) * 4608;
        const uint32_t* V  = Vs + ((NT - 1) & 3) * VTILE_U;
#pragma unroll
        for (int ksq = 0; ksq < 4; ++ksq)
            pv_chunk(Pr, V, o, q0b, g, tg, nj, ksq);
    }

    // Row-sum reduction
#pragma unroll
    for (int mt = 0; mt < 4; ++mt)
#pragma unroll
        for (int h = 0; h < 2; ++h) {
            float v = lsum[mt][h];
            v += __shfl_xor_sync(0xffffffffu, v, 1);
            v += __shfl_xor_sync(0xffffffffu, v, 2);
            if (tg == 0) atomicAdd(&Lr[q0b + mt * 16 + h * 8 + g], v);
        }
    __syncthreads();

    const float gam = gamma[0];
#pragma unroll
    for (int mt = 0; mt < 4; ++mt) {
        const float s0 = gam / Lr[q0b + mt * 16 + g];
        const float s1 = gam / Lr[q0b + mt * 16 + 8 + g];
        const int qg = n0 + q0b + mt * 16 + g;
#pragma unroll
        for (int nt = 0; nt < 8; ++nt) {
            int c  = nj * 64 + nt * 8 + 2 * tg;
            int i0 = (b * CCH + c) * NN + qg;
            out[i0]          = o[mt][nt][0] * s0 + t_in[i0];
            out[i0 + NN]     = o[mt][nt][1] * s0 + t_in[i0 + NN];
            out[i0 + 8]      = o[mt][nt][2] * s1 + t_in[i0 + 8];
            out[i0 + NN + 8] = o[mt][nt][3] * s1 + t_in[i0 + NN + 8];
        }
    }
}

// ---------------------------------------------------------------------------
extern "C" void kernel_launch(void* const* d_in, const int* in_sizes, int n_in,
                              void* d_out, int out_size)
{
    const float* t_in  = (const float*)d_in[0];
    const float* f_w   = (const float*)d_in[1];
    const float* f_b   = (const float*)d_in[2];
    const float* g_w   = (const float*)d_in[3];
    const float* g_b   = (const float*)d_in[4];
    const float* h_w   = (const float*)d_in[5];
    const float* h_b   = (const float*)d_in[6];
    const float* gamma = (const float*)d_in[7];
    float* out = (float*)d_out;

    cudaFuncSetAttribute(proj_kernel,
                         cudaFuncAttributeMaxDynamicSharedMemorySize, PJ_SMEM);
    cudaFuncSetAttribute(attn_kernel,
                         cudaFuncAttributeMaxDynamicSharedMemorySize, SB_TOTAL);

    proj_kernel<<<dim3(64, BB), 256, PJ_SMEM>>>(t_in, f_w, f_b, g_w, g_b, h_w, h_b);
    attn_kernel<<<dim3(NN / TQ, BB), 256, SB_TOTAL>>>(t_in, gamma, out);
}